// round 5
// baseline (speedup 1.0000x reference)
#include <cuda_runtime.h>
#include <cuda_bf16.h>
#include <cstdint>

#define SEQ   2048
#define BATCH 128
#define INDIM 128
#define HID   256

// Scratch for the precomputed input projection xin[s][b][h] (256 MB).
__device__ float g_xin[(size_t)SEQ * BATCH * HID];

// ---------------------------------------------------------------------------
// Packed fp32x2 helpers
// ---------------------------------------------------------------------------
__device__ __forceinline__ void ffma2(unsigned long long& d,
                                      unsigned long long a,
                                      unsigned long long b) {
    asm("fma.rn.f32x2 %0, %1, %2, %0;" : "+l"(d) : "l"(a), "l"(b));
}
__device__ __forceinline__ unsigned long long dup2(float x) {
    unsigned long long r;
    asm("mov.b64 %0, {%1, %1};" : "=l"(r) : "f"(x));
    return r;
}
__device__ __forceinline__ float sum2(unsigned long long v) {
    return __uint_as_float((unsigned)v) + __uint_as_float((unsigned)(v >> 32));
}

// ---------------------------------------------------------------------------
// Kernel 1: xin = x @ W_in^T + b_in   (packed-f32x2 microkernel) — unchanged
// ---------------------------------------------------------------------------
#define GM_BM 128
#define GM_BN 128
#define GM_BK 16

__global__ __launch_bounds__(256) void xin_gemm_kernel(
    const float* __restrict__ X,
    const float* __restrict__ Win,
    const float* __restrict__ bin)
{
    __shared__ float As[GM_BK][GM_BM + 8];
    __shared__ float Bs[GM_BK][GM_BN + 8];

    const int tid = threadIdx.x;
    const size_t m0 = (size_t)blockIdx.x * GM_BM;
    const int    n0 = blockIdx.y * GM_BN;

    const int tx = tid & 15;
    const int ty = tid >> 4;

    const int lr = tid >> 2;
    const int lc = (tid & 3) * 4;

    unsigned long long acc[8][4];
#pragma unroll
    for (int i = 0; i < 8; i++)
#pragma unroll
        for (int jp = 0; jp < 4; jp++) acc[i][jp] = 0ull;

#pragma unroll
    for (int k0 = 0; k0 < INDIM; k0 += GM_BK) {
        const float4 a0 = *(const float4*)&X[(m0 + lr) * INDIM + k0 + lc];
        const float4 a1 = *(const float4*)&X[(m0 + lr + 64) * INDIM + k0 + lc];
        const float4 w0 = *(const float4*)&Win[(size_t)(n0 + lr) * INDIM + k0 + lc];
        const float4 w1 = *(const float4*)&Win[(size_t)(n0 + lr + 64) * INDIM + k0 + lc];

        __syncthreads();

        As[lc + 0][lr] = a0.x; As[lc + 1][lr] = a0.y;
        As[lc + 2][lr] = a0.z; As[lc + 3][lr] = a0.w;
        As[lc + 0][lr + 64] = a1.x; As[lc + 1][lr + 64] = a1.y;
        As[lc + 2][lr + 64] = a1.z; As[lc + 3][lr + 64] = a1.w;

        Bs[lc + 0][lr] = w0.x; Bs[lc + 1][lr] = w0.y;
        Bs[lc + 2][lr] = w0.z; Bs[lc + 3][lr] = w0.w;
        Bs[lc + 0][lr + 64] = w1.x; Bs[lc + 1][lr + 64] = w1.y;
        Bs[lc + 2][lr + 64] = w1.z; Bs[lc + 3][lr + 64] = w1.w;

        __syncthreads();

#pragma unroll
        for (int k = 0; k < GM_BK; k++) {
            float ar[8];
            float4 t;
            t = *(const float4*)&As[k][ty * 8 + 0];
            ar[0] = t.x; ar[1] = t.y; ar[2] = t.z; ar[3] = t.w;
            t = *(const float4*)&As[k][ty * 8 + 4];
            ar[4] = t.x; ar[5] = t.y; ar[6] = t.z; ar[7] = t.w;

            const ulonglong2 b01 = *(const ulonglong2*)&Bs[k][tx * 8 + 0];
            const ulonglong2 b23 = *(const ulonglong2*)&Bs[k][tx * 8 + 4];

#pragma unroll
            for (int i = 0; i < 8; i++) {
                const unsigned long long ad = dup2(ar[i]);
                ffma2(acc[i][0], ad, b01.x);
                ffma2(acc[i][1], ad, b01.y);
                ffma2(acc[i][2], ad, b23.x);
                ffma2(acc[i][3], ad, b23.y);
            }
        }
    }

    float bn[8];
#pragma unroll
    for (int jj = 0; jj < 8; jj++) bn[jj] = bin[n0 + tx * 8 + jj];

#pragma unroll
    for (int i = 0; i < 8; i++) {
        const size_t m = m0 + ty * 8 + i;
        float4 o0, o1;
        o0.x = __uint_as_float((unsigned)acc[i][0]) + bn[0];
        o0.y = __uint_as_float((unsigned)(acc[i][0] >> 32)) + bn[1];
        o0.z = __uint_as_float((unsigned)acc[i][1]) + bn[2];
        o0.w = __uint_as_float((unsigned)(acc[i][1] >> 32)) + bn[3];
        o1.x = __uint_as_float((unsigned)acc[i][2]) + bn[4];
        o1.y = __uint_as_float((unsigned)(acc[i][2] >> 32)) + bn[5];
        o1.z = __uint_as_float((unsigned)acc[i][3]) + bn[6];
        o1.w = __uint_as_float((unsigned)(acc[i][3] >> 32)) + bn[7];
        *(float4*)&g_xin[m * HID + n0 + tx * 8 + 0] = o0;
        *(float4*)&g_xin[m * HID + n0 + tx * 8 + 4] = o1;
    }
}

// ---------------------------------------------------------------------------
// Kernel 2: persistent scan — 512 threads, 16 warps (4 per SMSP).
// Warp w owns j in [16w, 16w+16). Lane = (g = lane>>2, ji = lane&3).
// Thread computes 4 outputs j = 16w + 4m + ji over its 32-k subset
// {32L + 4g .. +3 : L = 0..7}. Per line L, ONE LDS.128 covers the whole
// 128B h line (8 g-lanes x 16B, ji broadcast) -> 8 h wavefronts/warp/step.
// W: k-lines 0..2 in smem (96 KB, thread-private 16B chunks), lines 3..7 in
// registers (40 u64). Reduce over g with 3 butterfly shuffles (4/8/16).
// xin prefetched into a smem ring by threads 0..255.
// ---------------------------------------------------------------------------
#define SCAN_THREADS 512
#define WSM_LINES 3           // k-lines 0..2 from smem
#define WREG_LINES 5          // k-lines 3..7 from registers

__global__ __launch_bounds__(SCAN_THREADS, 1) void ctrnn_scan_kernel(
    const float* __restrict__ h0,
    const float* __restrict__ Wh,
    const float* __restrict__ bh,
    float* __restrict__ out,
    long long out_size)
{
    extern __shared__ ulonglong2 Wsm[];              // 12*512 float4 = 96 KB
    __shared__ __align__(128) float hbuf[2][HID];    // double-buffered h
    __shared__ float xring[2][HID];                  // xin prefetch ring

    const int tid  = threadIdx.x;
    const int b    = blockIdx.x;
    const int w    = tid >> 5;        // 0..15
    const int lane = tid & 31;
    const int g    = lane >> 2;       // 0..7  (k-group)
    const int ji   = lane & 3;        // 0..3

    // ---- stage W: smem part (k-lines 0..2), thread-private 16B chunks ----
#pragma unroll
    for (int m = 0; m < 4; m++) {
        const int j = 16 * w + 4 * m + ji;
        const float* wr = Wh + (size_t)j * HID;
#pragma unroll
        for (int L = 0; L < WSM_LINES; L++)
            Wsm[(L * 4 + m) * SCAN_THREADS + tid] =
                *(const ulonglong2*)&wr[32 * L + 4 * g];
    }

    // ---- stage W: register part (k-lines 3..7) ----
    unsigned long long wreg[4][WREG_LINES][2];
#pragma unroll
    for (int m = 0; m < 4; m++) {
        const int j = 16 * w + 4 * m + ji;
        const float* wr = Wh + (size_t)j * HID;
#pragma unroll
        for (int L = 0; L < WREG_LINES; L++) {
            const ulonglong2 v =
                *(const ulonglong2*)&wr[32 * (L + WSM_LINES) + 4 * g];
            wreg[m][L][0] = v.x;
            wreg[m][L][1] = v.y;
        }
    }

    float bhm[4], hprev[4];
#pragma unroll
    for (int m = 0; m < 4; m++) {
        const int j = 16 * w + 4 * m + ji;
        bhm[m]   = bh[j];
        hprev[m] = h0[(size_t)b * HID + j];
    }

    const float* __restrict__ xin_b = g_xin + (size_t)b * HID;
    float* __restrict__ out_b = out + (size_t)b * HID;
    const size_t ss = (size_t)BATCH * HID;

    if (tid < HID) {
        hbuf[0][tid]  = h0[(size_t)b * HID + tid];
        xring[0][tid] = __ldg(&xin_b[tid]);           // xin for t = 0
    }
    __syncthreads();

    int p = 0;
    for (int t = 0; t < SEQ; t++) {
        const ulonglong2* __restrict__ C2 = (const ulonglong2*)hbuf[p];
        float* __restrict__ nxt = hbuf[p ^ 1];

        // prefetch next step's xin into a register (threads 0..255)
        float xnext = 0.0f;
        if (tid < HID) {
            const int tn = (t + 1 < SEQ) ? (t + 1) : t;
            xnext = __ldg(&xin_b[(size_t)tn * ss + tid]);
        }

        unsigned long long acc[4] = {0ull, 0ull, 0ull, 0ull};

#pragma unroll
        for (int L = 0; L < 8; L++) {
            // one 128B line per instruction across the 8 g-lanes
            const ulonglong2 hv = C2[8 * L + g];
            if (L < WSM_LINES) {
#pragma unroll
                for (int m = 0; m < 4; m++) {
                    const ulonglong2 wv = Wsm[(L * 4 + m) * SCAN_THREADS + tid];
                    ffma2(acc[m], wv.x, hv.x);
                    ffma2(acc[m], wv.y, hv.y);
                }
            } else {
#pragma unroll
                for (int m = 0; m < 4; m++) {
                    ffma2(acc[m], wreg[m][L - WSM_LINES][0], hv.x);
                    ffma2(acc[m], wreg[m][L - WSM_LINES][1], hv.y);
                }
            }
        }

        // reduce across the 8 k-groups (lane bits 2,3,4)
        float s[4];
#pragma unroll
        for (int m = 0; m < 4; m++) {
            float v = sum2(acc[m]);
            v += __shfl_xor_sync(0xffffffffu, v, 4, 32);
            v += __shfl_xor_sync(0xffffffffu, v, 8, 32);
            v += __shfl_xor_sync(0xffffffffu, v, 16, 32);
            s[m] = v;
        }

        if (g == 0) {
#pragma unroll
            for (int m = 0; m < 4; m++) {
                const int j = 16 * w + 4 * m + ji;
                const float y  = s[m] + xring[t & 1][j] + bhm[m];
                const float hn = fmaf(fmaxf(y, 0.0f), 0.1f, 0.9f * hprev[m]);
                hprev[m] = hn;
                nxt[j] = hn;
                out_b[(size_t)t * ss + j] = hn;
            }
        }
        if (tid < HID) xring[(t + 1) & 1][tid] = xnext;
        p ^= 1;
        __syncthreads();
    }

    // h_final appended after outputs
    const long long main_elems = (long long)SEQ * BATCH * HID;
    if (g == 0 && out_size >= main_elems + (long long)BATCH * HID) {
#pragma unroll
        for (int m = 0; m < 4; m++)
            out[main_elems + (size_t)b * HID + 16 * w + 4 * m + ji] = hprev[m];
    }
}

// ---------------------------------------------------------------------------
// Launcher.  Inputs (metadata order): x, h0, W_in, b_in, W_h, b_h
// ---------------------------------------------------------------------------
extern "C" void kernel_launch(void* const* d_in, const int* in_sizes, int n_in,
                              void* d_out, int out_size)
{
    const float* x    = (const float*)d_in[0];
    const float* h0   = (const float*)d_in[1];
    const float* Win  = (const float*)d_in[2];
    const float* bin  = (const float*)d_in[3];
    const float* Wh   = (const float*)d_in[4];
    const float* bhp  = (const float*)d_in[5];
    float* out = (float*)d_out;

    const int scan_smem = WSM_LINES * 4 * SCAN_THREADS * (int)sizeof(ulonglong2); // 96 KB
    cudaFuncSetAttribute(ctrnn_scan_kernel,
                         cudaFuncAttributeMaxDynamicSharedMemorySize,
                         scan_smem);

    dim3 g1((SEQ * BATCH) / GM_BM, HID / GM_BN);
    xin_gemm_kernel<<<g1, 256>>>(x, Win, bin);

    ctrnn_scan_kernel<<<BATCH, SCAN_THREADS, scan_smem>>>(
        h0, Wh, bhp, out, (long long)out_size);
}

// round 6
// speedup vs baseline: 1.1579x; 1.1579x over previous
#include <cuda_runtime.h>
#include <cuda_bf16.h>
#include <cstdint>

#define SEQ   2048
#define BATCH 128
#define INDIM 128
#define HID   256

// Scratch for the precomputed input projection xin[s][b][h] (256 MB).
__device__ float g_xin[(size_t)SEQ * BATCH * HID];

// ---------------------------------------------------------------------------
// Packed fp32x2 helpers
// ---------------------------------------------------------------------------
__device__ __forceinline__ void ffma2(unsigned long long& d,
                                      unsigned long long a,
                                      unsigned long long b) {
    asm("fma.rn.f32x2 %0, %1, %2, %0;" : "+l"(d) : "l"(a), "l"(b));
}
__device__ __forceinline__ unsigned long long dup2(float x) {
    unsigned long long r;
    asm("mov.b64 %0, {%1, %1};" : "=l"(r) : "f"(x));
    return r;
}
__device__ __forceinline__ float sum2(unsigned long long v) {
    return __uint_as_float((unsigned)v) + __uint_as_float((unsigned)(v >> 32));
}

// ---------------------------------------------------------------------------
// Kernel 1: xin = x @ W_in^T + b_in   (packed-f32x2 microkernel) — unchanged
// ---------------------------------------------------------------------------
#define GM_BM 128
#define GM_BN 128
#define GM_BK 16

__global__ __launch_bounds__(256) void xin_gemm_kernel(
    const float* __restrict__ X,
    const float* __restrict__ Win,
    const float* __restrict__ bin)
{
    __shared__ float As[GM_BK][GM_BM + 8];
    __shared__ float Bs[GM_BK][GM_BN + 8];

    const int tid = threadIdx.x;
    const size_t m0 = (size_t)blockIdx.x * GM_BM;
    const int    n0 = blockIdx.y * GM_BN;

    const int tx = tid & 15;
    const int ty = tid >> 4;

    const int lr = tid >> 2;
    const int lc = (tid & 3) * 4;

    unsigned long long acc[8][4];
#pragma unroll
    for (int i = 0; i < 8; i++)
#pragma unroll
        for (int jp = 0; jp < 4; jp++) acc[i][jp] = 0ull;

#pragma unroll
    for (int k0 = 0; k0 < INDIM; k0 += GM_BK) {
        const float4 a0 = *(const float4*)&X[(m0 + lr) * INDIM + k0 + lc];
        const float4 a1 = *(const float4*)&X[(m0 + lr + 64) * INDIM + k0 + lc];
        const float4 w0 = *(const float4*)&Win[(size_t)(n0 + lr) * INDIM + k0 + lc];
        const float4 w1 = *(const float4*)&Win[(size_t)(n0 + lr + 64) * INDIM + k0 + lc];

        __syncthreads();

        As[lc + 0][lr] = a0.x; As[lc + 1][lr] = a0.y;
        As[lc + 2][lr] = a0.z; As[lc + 3][lr] = a0.w;
        As[lc + 0][lr + 64] = a1.x; As[lc + 1][lr + 64] = a1.y;
        As[lc + 2][lr + 64] = a1.z; As[lc + 3][lr + 64] = a1.w;

        Bs[lc + 0][lr] = w0.x; Bs[lc + 1][lr] = w0.y;
        Bs[lc + 2][lr] = w0.z; Bs[lc + 3][lr] = w0.w;
        Bs[lc + 0][lr + 64] = w1.x; Bs[lc + 1][lr + 64] = w1.y;
        Bs[lc + 2][lr + 64] = w1.z; Bs[lc + 3][lr + 64] = w1.w;

        __syncthreads();

#pragma unroll
        for (int k = 0; k < GM_BK; k++) {
            float ar[8];
            float4 t;
            t = *(const float4*)&As[k][ty * 8 + 0];
            ar[0] = t.x; ar[1] = t.y; ar[2] = t.z; ar[3] = t.w;
            t = *(const float4*)&As[k][ty * 8 + 4];
            ar[4] = t.x; ar[5] = t.y; ar[6] = t.z; ar[7] = t.w;

            const ulonglong2 b01 = *(const ulonglong2*)&Bs[k][tx * 8 + 0];
            const ulonglong2 b23 = *(const ulonglong2*)&Bs[k][tx * 8 + 4];

#pragma unroll
            for (int i = 0; i < 8; i++) {
                const unsigned long long ad = dup2(ar[i]);
                ffma2(acc[i][0], ad, b01.x);
                ffma2(acc[i][1], ad, b01.y);
                ffma2(acc[i][2], ad, b23.x);
                ffma2(acc[i][3], ad, b23.y);
            }
        }
    }

    float bn[8];
#pragma unroll
    for (int jj = 0; jj < 8; jj++) bn[jj] = bin[n0 + tx * 8 + jj];

#pragma unroll
    for (int i = 0; i < 8; i++) {
        const size_t m = m0 + ty * 8 + i;
        float4 o0, o1;
        o0.x = __uint_as_float((unsigned)acc[i][0]) + bn[0];
        o0.y = __uint_as_float((unsigned)(acc[i][0] >> 32)) + bn[1];
        o0.z = __uint_as_float((unsigned)acc[i][1]) + bn[2];
        o0.w = __uint_as_float((unsigned)(acc[i][1] >> 32)) + bn[3];
        o1.x = __uint_as_float((unsigned)acc[i][2]) + bn[4];
        o1.y = __uint_as_float((unsigned)(acc[i][2] >> 32)) + bn[5];
        o1.z = __uint_as_float((unsigned)acc[i][3]) + bn[6];
        o1.w = __uint_as_float((unsigned)(acc[i][3] >> 32)) + bn[7];
        *(float4*)&g_xin[m * HID + n0 + tx * 8 + 0] = o0;
        *(float4*)&g_xin[m * HID + n0 + tx * 8 + 4] = o1;
    }
}

// ---------------------------------------------------------------------------
// Kernel 2: persistent scan — 512 threads, 16 warps (4 per SMSP).
// Warp w owns j in [16w, 16w+16). Lane = (g = lane>>3 in 0..3, ji = lane&7).
// Thread computes 2 outputs j = 16w + 8m + ji (m = 0..1) over its 64-k subset
// {32L + 8g + e : L = 0..7, e = 0..7}. Each h-load instruction covers ONE
// 128B line (4 g-chunks x 16B, 8-way ji broadcast) -> 1 wavefront.
// W: k-lines 0..1 in smem (64 KB, thread-private 128B chunks, = R4 traffic),
//    k-lines 2..7 in registers (48 u64 = 96 regs; RF-exact at 512 threads).
// Reduce over 4 k-groups = 2 butterfly shuffles (all-reduce).
// ---------------------------------------------------------------------------
#define SCAN_THREADS 512
#define WSM_LINES 2           // k-lines 0..1 from smem
#define WREG_LINES 6          // k-lines 2..7 from registers

__global__ __launch_bounds__(SCAN_THREADS, 1) void ctrnn_scan_kernel(
    const float* __restrict__ h0,
    const float* __restrict__ Wh,
    const float* __restrict__ bh,
    float* __restrict__ out,
    long long out_size)
{
    extern __shared__ float4 Wsm4[];                 // 8 * 512 float4 = 64 KB
    __shared__ __align__(128) float hbuf[2][HID];    // double-buffered h
    __shared__ float xring[2][HID];                  // xin prefetch ring

    const int tid  = threadIdx.x;
    const int b    = blockIdx.x;
    const int w    = tid >> 5;        // 0..15
    const int lane = tid & 31;
    const int g    = lane >> 3;       // 0..3  (k-group)
    const int ji   = lane & 7;        // 0..7

    // ---- stage W: smem part (k-lines 0..1), thread-private 128B chunks ----
    // chunk c = ((L*2 + m)*2 + q), q = float4 half; Wsm4[c*512 + tid]
#pragma unroll
    for (int m = 0; m < 2; m++) {
        const int j = 16 * w + 8 * m + ji;
        const float* wr = Wh + (size_t)j * HID;
#pragma unroll
        for (int L = 0; L < WSM_LINES; L++)
#pragma unroll
            for (int q = 0; q < 2; q++)
                Wsm4[(((L * 2 + m) * 2) + q) * SCAN_THREADS + tid] =
                    *(const float4*)&wr[32 * L + 8 * g + 4 * q];
    }

    // ---- stage W: register part (k-lines 2..7): 2m x 6L x 4 u64 = 48 u64 ----
    unsigned long long wreg[2][WREG_LINES][4];
#pragma unroll
    for (int m = 0; m < 2; m++) {
        const int j = 16 * w + 8 * m + ji;
        const float* wr = Wh + (size_t)j * HID;
#pragma unroll
        for (int L = 0; L < WREG_LINES; L++) {
            const ulonglong2 va =
                *(const ulonglong2*)&wr[32 * (L + WSM_LINES) + 8 * g];
            const ulonglong2 vb =
                *(const ulonglong2*)&wr[32 * (L + WSM_LINES) + 8 * g + 4];
            wreg[m][L][0] = va.x; wreg[m][L][1] = va.y;
            wreg[m][L][2] = vb.x; wreg[m][L][3] = vb.y;
        }
    }

    float bhm[2], hprev[2];
#pragma unroll
    for (int m = 0; m < 2; m++) {
        const int j = 16 * w + 8 * m + ji;
        bhm[m]   = bh[j];
        hprev[m] = h0[(size_t)b * HID + j];
    }

    const float* __restrict__ xin_b = g_xin + (size_t)b * HID;
    float* __restrict__ out_b = out + (size_t)b * HID;
    const size_t ss = (size_t)BATCH * HID;

    if (tid < HID) {
        hbuf[0][tid]  = h0[(size_t)b * HID + tid];
        xring[0][tid] = __ldg(&xin_b[tid]);           // xin for t = 0
    }
    __syncthreads();

    int p = 0;
    for (int t = 0; t < SEQ; t++) {
        const ulonglong2* __restrict__ C2 = (const ulonglong2*)hbuf[p];
        float* __restrict__ nxt = hbuf[p ^ 1];

        // prefetch next step's xin into a register (threads 0..255)
        float xnext = 0.0f;
        if (tid < HID) {
            const int tn = (t + 1 < SEQ) ? (t + 1) : t;
            xnext = __ldg(&xin_b[(size_t)tn * ss + tid]);
        }

        // 4 rotating accumulators: [m][L-parity]
        unsigned long long acc[2][2] = {{0ull, 0ull}, {0ull, 0ull}};

#pragma unroll
        for (int L = 0; L < 8; L++) {
            // thread's 8 h values on line L: 2 x LDS.128, 1 wavefront each
            const ulonglong2 ha = C2[8 * L + 2 * g + 0];
            const ulonglong2 hb = C2[8 * L + 2 * g + 1];
            const int par = L & 1;

            if (L < WSM_LINES) {
#pragma unroll
                for (int m = 0; m < 2; m++) {
                    const ulonglong2 wa = *(const ulonglong2*)
                        &Wsm4[(((L * 2 + m) * 2) + 0) * SCAN_THREADS + tid];
                    const ulonglong2 wb = *(const ulonglong2*)
                        &Wsm4[(((L * 2 + m) * 2) + 1) * SCAN_THREADS + tid];
                    ffma2(acc[m][par], wa.x, ha.x);
                    ffma2(acc[m][par], wa.y, ha.y);
                    ffma2(acc[m][par], wb.x, hb.x);
                    ffma2(acc[m][par], wb.y, hb.y);
                }
            } else {
#pragma unroll
                for (int m = 0; m < 2; m++) {
                    ffma2(acc[m][par], wreg[m][L - WSM_LINES][0], ha.x);
                    ffma2(acc[m][par], wreg[m][L - WSM_LINES][1], ha.y);
                    ffma2(acc[m][par], wreg[m][L - WSM_LINES][2], hb.x);
                    ffma2(acc[m][par], wreg[m][L - WSM_LINES][3], hb.y);
                }
            }
        }

        // all-reduce across the 4 k-groups (lane bits 3,4)
        float s[2];
#pragma unroll
        for (int m = 0; m < 2; m++) {
            float v = sum2(acc[m][0]) + sum2(acc[m][1]);
            v += __shfl_xor_sync(0xffffffffu, v, 8, 32);
            v += __shfl_xor_sync(0xffffffffu, v, 16, 32);
            s[m] = v;
        }

        // epilogue: every lane has the sums; stores predicated to g==0
#pragma unroll
        for (int m = 0; m < 2; m++) {
            const int j = 16 * w + 8 * m + ji;
            const float y  = s[m] + xring[t & 1][j] + bhm[m];
            const float hn = fmaf(fmaxf(y, 0.0f), 0.1f, 0.9f * hprev[m]);
            hprev[m] = hn;
            if (g == 0) {
                nxt[j] = hn;
                out_b[(size_t)t * ss + j] = hn;
            }
        }
        if (tid < HID) xring[(t + 1) & 1][tid] = xnext;
        p ^= 1;
        __syncthreads();
    }

    // h_final appended after outputs
    const long long main_elems = (long long)SEQ * BATCH * HID;
    if (g == 0 && out_size >= main_elems + (long long)BATCH * HID) {
#pragma unroll
        for (int m = 0; m < 2; m++)
            out[main_elems + (size_t)b * HID + 16 * w + 8 * m + ji] = hprev[m];
    }
}

// ---------------------------------------------------------------------------
// Launcher.  Inputs (metadata order): x, h0, W_in, b_in, W_h, b_h
// ---------------------------------------------------------------------------
extern "C" void kernel_launch(void* const* d_in, const int* in_sizes, int n_in,
                              void* d_out, int out_size)
{
    const float* x    = (const float*)d_in[0];
    const float* h0   = (const float*)d_in[1];
    const float* Win  = (const float*)d_in[2];
    const float* bin  = (const float*)d_in[3];
    const float* Wh   = (const float*)d_in[4];
    const float* bhp  = (const float*)d_in[5];
    float* out = (float*)d_out;

    const int scan_smem = 8 * SCAN_THREADS * (int)sizeof(float4);   // 64 KB
    cudaFuncSetAttribute(ctrnn_scan_kernel,
                         cudaFuncAttributeMaxDynamicSharedMemorySize,
                         scan_smem);

    dim3 g1((SEQ * BATCH) / GM_BM, HID / GM_BN);
    xin_gemm_kernel<<<g1, 256>>>(x, Win, bin);

    ctrnn_scan_kernel<<<BATCH, SCAN_THREADS, scan_smem>>>(
        h0, Wh, bhp, out, (long long)out_size);
}

// round 7
// speedup vs baseline: 1.1602x; 1.0020x over previous
#include <cuda_runtime.h>
#include <cuda_bf16.h>
#include <cstdint>

#define SEQ   2048
#define BATCH 128
#define INDIM 128
#define HID   256

// Scratch for the precomputed input projection xin[s][b][h] (256 MB).
__device__ float g_xin[(size_t)SEQ * BATCH * HID];

// ---------------------------------------------------------------------------
// Packed fp32x2 helpers
// ---------------------------------------------------------------------------
__device__ __forceinline__ void ffma2(unsigned long long& d,
                                      unsigned long long a,
                                      unsigned long long b) {
    asm("fma.rn.f32x2 %0, %1, %2, %0;" : "+l"(d) : "l"(a), "l"(b));
}
__device__ __forceinline__ unsigned long long dup2(float x) {
    unsigned long long r;
    asm("mov.b64 %0, {%1, %1};" : "=l"(r) : "f"(x));
    return r;
}
__device__ __forceinline__ float sum2(unsigned long long v) {
    return __uint_as_float((unsigned)v) + __uint_as_float((unsigned)(v >> 32));
}

// ---------------------------------------------------------------------------
// Kernel 1: xin = x @ W_in^T + b_in   (packed-f32x2 microkernel) — unchanged
// ---------------------------------------------------------------------------
#define GM_BM 128
#define GM_BN 128
#define GM_BK 16

__global__ __launch_bounds__(256) void xin_gemm_kernel(
    const float* __restrict__ X,
    const float* __restrict__ Win,
    const float* __restrict__ bin)
{
    __shared__ float As[GM_BK][GM_BM + 8];
    __shared__ float Bs[GM_BK][GM_BN + 8];

    const int tid = threadIdx.x;
    const size_t m0 = (size_t)blockIdx.x * GM_BM;
    const int    n0 = blockIdx.y * GM_BN;

    const int tx = tid & 15;
    const int ty = tid >> 4;

    const int lr = tid >> 2;
    const int lc = (tid & 3) * 4;

    unsigned long long acc[8][4];
#pragma unroll
    for (int i = 0; i < 8; i++)
#pragma unroll
        for (int jp = 0; jp < 4; jp++) acc[i][jp] = 0ull;

#pragma unroll
    for (int k0 = 0; k0 < INDIM; k0 += GM_BK) {
        const float4 a0 = *(const float4*)&X[(m0 + lr) * INDIM + k0 + lc];
        const float4 a1 = *(const float4*)&X[(m0 + lr + 64) * INDIM + k0 + lc];
        const float4 w0 = *(const float4*)&Win[(size_t)(n0 + lr) * INDIM + k0 + lc];
        const float4 w1 = *(const float4*)&Win[(size_t)(n0 + lr + 64) * INDIM + k0 + lc];

        __syncthreads();

        As[lc + 0][lr] = a0.x; As[lc + 1][lr] = a0.y;
        As[lc + 2][lr] = a0.z; As[lc + 3][lr] = a0.w;
        As[lc + 0][lr + 64] = a1.x; As[lc + 1][lr + 64] = a1.y;
        As[lc + 2][lr + 64] = a1.z; As[lc + 3][lr + 64] = a1.w;

        Bs[lc + 0][lr] = w0.x; Bs[lc + 1][lr] = w0.y;
        Bs[lc + 2][lr] = w0.z; Bs[lc + 3][lr] = w0.w;
        Bs[lc + 0][lr + 64] = w1.x; Bs[lc + 1][lr + 64] = w1.y;
        Bs[lc + 2][lr + 64] = w1.z; Bs[lc + 3][lr + 64] = w1.w;

        __syncthreads();

#pragma unroll
        for (int k = 0; k < GM_BK; k++) {
            float ar[8];
            float4 t;
            t = *(const float4*)&As[k][ty * 8 + 0];
            ar[0] = t.x; ar[1] = t.y; ar[2] = t.z; ar[3] = t.w;
            t = *(const float4*)&As[k][ty * 8 + 4];
            ar[4] = t.x; ar[5] = t.y; ar[6] = t.z; ar[7] = t.w;

            const ulonglong2 b01 = *(const ulonglong2*)&Bs[k][tx * 8 + 0];
            const ulonglong2 b23 = *(const ulonglong2*)&Bs[k][tx * 8 + 4];

#pragma unroll
            for (int i = 0; i < 8; i++) {
                const unsigned long long ad = dup2(ar[i]);
                ffma2(acc[i][0], ad, b01.x);
                ffma2(acc[i][1], ad, b01.y);
                ffma2(acc[i][2], ad, b23.x);
                ffma2(acc[i][3], ad, b23.y);
            }
        }
    }

    float bn[8];
#pragma unroll
    for (int jj = 0; jj < 8; jj++) bn[jj] = bin[n0 + tx * 8 + jj];

#pragma unroll
    for (int i = 0; i < 8; i++) {
        const size_t m = m0 + ty * 8 + i;
        float4 o0, o1;
        o0.x = __uint_as_float((unsigned)acc[i][0]) + bn[0];
        o0.y = __uint_as_float((unsigned)(acc[i][0] >> 32)) + bn[1];
        o0.z = __uint_as_float((unsigned)acc[i][1]) + bn[2];
        o0.w = __uint_as_float((unsigned)(acc[i][1] >> 32)) + bn[3];
        o1.x = __uint_as_float((unsigned)acc[i][2]) + bn[4];
        o1.y = __uint_as_float((unsigned)(acc[i][2] >> 32)) + bn[5];
        o1.z = __uint_as_float((unsigned)acc[i][3]) + bn[6];
        o1.w = __uint_as_float((unsigned)(acc[i][3] >> 32)) + bn[7];
        *(float4*)&g_xin[m * HID + n0 + tx * 8 + 0] = o0;
        *(float4*)&g_xin[m * HID + n0 + tx * 8 + 4] = o1;
    }
}

// ---------------------------------------------------------------------------
// Kernel 2: persistent scan — 512 threads, 16 warps (4 per SMSP).
// Warp w owns j in [16w, 16w+16). Lane = (g = lane>>3 in 0..3, ji = lane&7).
// Thread computes 2 outputs j = 16w + 8m + ji (m = 0..1) over its 64-k subset
// {32L + 8g + e : L = 0..7, e = 0..7}. Each h-load instruction covers ONE
// 128B line (4 g-chunks x 16B, 8-way ji broadcast) -> 1 wavefront.
// W: k-lines 0..1 in smem (64 KB, thread-private 128B chunks, = R4 traffic),
//    k-lines 2..7 in registers (48 u64 = 96 regs; RF-exact at 512 threads).
// Reduce over 4 k-groups = 2 butterfly shuffles (all-reduce).
// ---------------------------------------------------------------------------
#define SCAN_THREADS 512
#define WSM_LINES 2           // k-lines 0..1 from smem
#define WREG_LINES 6          // k-lines 2..7 from registers

__global__ __launch_bounds__(SCAN_THREADS, 1) void ctrnn_scan_kernel(
    const float* __restrict__ h0,
    const float* __restrict__ Wh,
    const float* __restrict__ bh,
    float* __restrict__ out,
    long long out_size)
{
    extern __shared__ float4 Wsm4[];                 // 8 * 512 float4 = 64 KB
    __shared__ __align__(128) float hbuf[2][HID];    // double-buffered h
    __shared__ float xring[2][HID];                  // xin prefetch ring

    const int tid  = threadIdx.x;
    const int b    = blockIdx.x;
    const int w    = tid >> 5;        // 0..15
    const int lane = tid & 31;
    const int g    = lane >> 3;       // 0..3  (k-group)
    const int ji   = lane & 7;        // 0..7

    // ---- stage W: smem part (k-lines 0..1), thread-private 128B chunks ----
    // chunk c = ((L*2 + m)*2 + q), q = float4 half; Wsm4[c*512 + tid]
#pragma unroll
    for (int m = 0; m < 2; m++) {
        const int j = 16 * w + 8 * m + ji;
        const float* wr = Wh + (size_t)j * HID;
#pragma unroll
        for (int L = 0; L < WSM_LINES; L++)
#pragma unroll
            for (int q = 0; q < 2; q++)
                Wsm4[(((L * 2 + m) * 2) + q) * SCAN_THREADS + tid] =
                    *(const float4*)&wr[32 * L + 8 * g + 4 * q];
    }

    // ---- stage W: register part (k-lines 2..7): 2m x 6L x 4 u64 = 48 u64 ----
    unsigned long long wreg[2][WREG_LINES][4];
#pragma unroll
    for (int m = 0; m < 2; m++) {
        const int j = 16 * w + 8 * m + ji;
        const float* wr = Wh + (size_t)j * HID;
#pragma unroll
        for (int L = 0; L < WREG_LINES; L++) {
            const ulonglong2 va =
                *(const ulonglong2*)&wr[32 * (L + WSM_LINES) + 8 * g];
            const ulonglong2 vb =
                *(const ulonglong2*)&wr[32 * (L + WSM_LINES) + 8 * g + 4];
            wreg[m][L][0] = va.x; wreg[m][L][1] = va.y;
            wreg[m][L][2] = vb.x; wreg[m][L][3] = vb.y;
        }
    }

    float bhm[2], hprev[2];
#pragma unroll
    for (int m = 0; m < 2; m++) {
        const int j = 16 * w + 8 * m + ji;
        bhm[m]   = bh[j];
        hprev[m] = h0[(size_t)b * HID + j];
    }

    const float* __restrict__ xin_b = g_xin + (size_t)b * HID;
    float* __restrict__ out_b = out + (size_t)b * HID;
    const size_t ss = (size_t)BATCH * HID;

    if (tid < HID) {
        hbuf[0][tid]  = h0[(size_t)b * HID + tid];
        xring[0][tid] = __ldg(&xin_b[tid]);           // xin for t = 0
    }
    __syncthreads();

    int p = 0;
    for (int t = 0; t < SEQ; t++) {
        const ulonglong2* __restrict__ C2 = (const ulonglong2*)hbuf[p];
        float* __restrict__ nxt = hbuf[p ^ 1];

        // prefetch next step's xin into a register (threads 0..255)
        float xnext = 0.0f;
        if (tid < HID) {
            const int tn = (t + 1 < SEQ) ? (t + 1) : t;
            xnext = __ldg(&xin_b[(size_t)tn * ss + tid]);
        }

        // 4 rotating accumulators: [m][L-parity]
        unsigned long long acc[2][2] = {{0ull, 0ull}, {0ull, 0ull}};

#pragma unroll
        for (int L = 0; L < 8; L++) {
            // thread's 8 h values on line L: 2 x LDS.128, 1 wavefront each
            const ulonglong2 ha = C2[8 * L + 2 * g + 0];
            const ulonglong2 hb = C2[8 * L + 2 * g + 1];
            const int par = L & 1;

            if (L < WSM_LINES) {
#pragma unroll
                for (int m = 0; m < 2; m++) {
                    const ulonglong2 wa = *(const ulonglong2*)
                        &Wsm4[(((L * 2 + m) * 2) + 0) * SCAN_THREADS + tid];
                    const ulonglong2 wb = *(const ulonglong2*)
                        &Wsm4[(((L * 2 + m) * 2) + 1) * SCAN_THREADS + tid];
                    ffma2(acc[m][par], wa.x, ha.x);
                    ffma2(acc[m][par], wa.y, ha.y);
                    ffma2(acc[m][par], wb.x, hb.x);
                    ffma2(acc[m][par], wb.y, hb.y);
                }
            } else {
#pragma unroll
                for (int m = 0; m < 2; m++) {
                    ffma2(acc[m][par], wreg[m][L - WSM_LINES][0], ha.x);
                    ffma2(acc[m][par], wreg[m][L - WSM_LINES][1], ha.y);
                    ffma2(acc[m][par], wreg[m][L - WSM_LINES][2], hb.x);
                    ffma2(acc[m][par], wreg[m][L - WSM_LINES][3], hb.y);
                }
            }
        }

        // all-reduce across the 4 k-groups (lane bits 3,4)
        float s[2];
#pragma unroll
        for (int m = 0; m < 2; m++) {
            float v = sum2(acc[m][0]) + sum2(acc[m][1]);
            v += __shfl_xor_sync(0xffffffffu, v, 8, 32);
            v += __shfl_xor_sync(0xffffffffu, v, 16, 32);
            s[m] = v;
        }

        // epilogue: every lane has the sums; stores predicated to g==0
#pragma unroll
        for (int m = 0; m < 2; m++) {
            const int j = 16 * w + 8 * m + ji;
            const float y  = s[m] + xring[t & 1][j] + bhm[m];
            const float hn = fmaf(fmaxf(y, 0.0f), 0.1f, 0.9f * hprev[m]);
            hprev[m] = hn;
            if (g == 0) {
                nxt[j] = hn;
                out_b[(size_t)t * ss + j] = hn;
            }
        }
        if (tid < HID) xring[(t + 1) & 1][tid] = xnext;
        p ^= 1;
        __syncthreads();
    }

    // h_final appended after outputs
    const long long main_elems = (long long)SEQ * BATCH * HID;
    if (g == 0 && out_size >= main_elems + (long long)BATCH * HID) {
#pragma unroll
        for (int m = 0; m < 2; m++)
            out[main_elems + (size_t)b * HID + 16 * w + 8 * m + ji] = hprev[m];
    }
}

// ---------------------------------------------------------------------------
// Launcher.  Inputs (metadata order): x, h0, W_in, b_in, W_h, b_h
// ---------------------------------------------------------------------------
extern "C" void kernel_launch(void* const* d_in, const int* in_sizes, int n_in,
                              void* d_out, int out_size)
{
    const float* x    = (const float*)d_in[0];
    const float* h0   = (const float*)d_in[1];
    const float* Win  = (const float*)d_in[2];
    const float* bin  = (const float*)d_in[3];
    const float* Wh   = (const float*)d_in[4];
    const float* bhp  = (const float*)d_in[5];
    float* out = (float*)d_out;

    const int scan_smem = 8 * SCAN_THREADS * (int)sizeof(float4);   // 64 KB
    cudaFuncSetAttribute(ctrnn_scan_kernel,
                         cudaFuncAttributeMaxDynamicSharedMemorySize,
                         scan_smem);

    dim3 g1((SEQ * BATCH) / GM_BM, HID / GM_BN);
    xin_gemm_kernel<<<g1, 256>>>(x, Win, bin);

    ctrnn_scan_kernel<<<BATCH, SCAN_THREADS, scan_smem>>>(
        h0, Wh, bhp, out, (long long)out_size);
}

// round 8
// speedup vs baseline: 1.1613x; 1.0009x over previous
#include <cuda_runtime.h>
#include <cuda_bf16.h>
#include <cstdint>

#define SEQ   2048
#define BATCH 128
#define INDIM 128
#define HID   256

// Scratch for the precomputed input projection xin[s][b][h] (256 MB).
__device__ float g_xin[(size_t)SEQ * BATCH * HID];

// ---------------------------------------------------------------------------
// Packed fp32x2 helpers
// ---------------------------------------------------------------------------
__device__ __forceinline__ void ffma2(unsigned long long& d,
                                      unsigned long long a,
                                      unsigned long long b) {
    asm("fma.rn.f32x2 %0, %1, %2, %0;" : "+l"(d) : "l"(a), "l"(b));
}
__device__ __forceinline__ unsigned long long dup2(float x) {
    unsigned long long r;
    asm("mov.b64 %0, {%1, %1};" : "=l"(r) : "f"(x));
    return r;
}
__device__ __forceinline__ float sum2(unsigned long long v) {
    return __uint_as_float((unsigned)v) + __uint_as_float((unsigned)(v >> 32));
}

// ---------------------------------------------------------------------------
// Kernel 1: xin = x @ W_in^T + b_in   (packed-f32x2 microkernel) — unchanged
// ---------------------------------------------------------------------------
#define GM_BM 128
#define GM_BN 128
#define GM_BK 16

__global__ __launch_bounds__(256) void xin_gemm_kernel(
    const float* __restrict__ X,
    const float* __restrict__ Win,
    const float* __restrict__ bin)
{
    __shared__ float As[GM_BK][GM_BM + 8];
    __shared__ float Bs[GM_BK][GM_BN + 8];

    const int tid = threadIdx.x;
    const size_t m0 = (size_t)blockIdx.x * GM_BM;
    const int    n0 = blockIdx.y * GM_BN;

    const int tx = tid & 15;
    const int ty = tid >> 4;

    const int lr = tid >> 2;
    const int lc = (tid & 3) * 4;

    unsigned long long acc[8][4];
#pragma unroll
    for (int i = 0; i < 8; i++)
#pragma unroll
        for (int jp = 0; jp < 4; jp++) acc[i][jp] = 0ull;

#pragma unroll
    for (int k0 = 0; k0 < INDIM; k0 += GM_BK) {
        const float4 a0 = *(const float4*)&X[(m0 + lr) * INDIM + k0 + lc];
        const float4 a1 = *(const float4*)&X[(m0 + lr + 64) * INDIM + k0 + lc];
        const float4 w0 = *(const float4*)&Win[(size_t)(n0 + lr) * INDIM + k0 + lc];
        const float4 w1 = *(const float4*)&Win[(size_t)(n0 + lr + 64) * INDIM + k0 + lc];

        __syncthreads();

        As[lc + 0][lr] = a0.x; As[lc + 1][lr] = a0.y;
        As[lc + 2][lr] = a0.z; As[lc + 3][lr] = a0.w;
        As[lc + 0][lr + 64] = a1.x; As[lc + 1][lr + 64] = a1.y;
        As[lc + 2][lr + 64] = a1.z; As[lc + 3][lr + 64] = a1.w;

        Bs[lc + 0][lr] = w0.x; Bs[lc + 1][lr] = w0.y;
        Bs[lc + 2][lr] = w0.z; Bs[lc + 3][lr] = w0.w;
        Bs[lc + 0][lr + 64] = w1.x; Bs[lc + 1][lr + 64] = w1.y;
        Bs[lc + 2][lr + 64] = w1.z; Bs[lc + 3][lr + 64] = w1.w;

        __syncthreads();

#pragma unroll
        for (int k = 0; k < GM_BK; k++) {
            float ar[8];
            float4 t;
            t = *(const float4*)&As[k][ty * 8 + 0];
            ar[0] = t.x; ar[1] = t.y; ar[2] = t.z; ar[3] = t.w;
            t = *(const float4*)&As[k][ty * 8 + 4];
            ar[4] = t.x; ar[5] = t.y; ar[6] = t.z; ar[7] = t.w;

            const ulonglong2 b01 = *(const ulonglong2*)&Bs[k][tx * 8 + 0];
            const ulonglong2 b23 = *(const ulonglong2*)&Bs[k][tx * 8 + 4];

#pragma unroll
            for (int i = 0; i < 8; i++) {
                const unsigned long long ad = dup2(ar[i]);
                ffma2(acc[i][0], ad, b01.x);
                ffma2(acc[i][1], ad, b01.y);
                ffma2(acc[i][2], ad, b23.x);
                ffma2(acc[i][3], ad, b23.y);
            }
        }
    }

    float bn[8];
#pragma unroll
    for (int jj = 0; jj < 8; jj++) bn[jj] = bin[n0 + tx * 8 + jj];

#pragma unroll
    for (int i = 0; i < 8; i++) {
        const size_t m = m0 + ty * 8 + i;
        float4 o0, o1;
        o0.x = __uint_as_float((unsigned)acc[i][0]) + bn[0];
        o0.y = __uint_as_float((unsigned)(acc[i][0] >> 32)) + bn[1];
        o0.z = __uint_as_float((unsigned)acc[i][1]) + bn[2];
        o0.w = __uint_as_float((unsigned)(acc[i][1] >> 32)) + bn[3];
        o1.x = __uint_as_float((unsigned)acc[i][2]) + bn[4];
        o1.y = __uint_as_float((unsigned)(acc[i][2] >> 32)) + bn[5];
        o1.z = __uint_as_float((unsigned)acc[i][3]) + bn[6];
        o1.w = __uint_as_float((unsigned)(acc[i][3] >> 32)) + bn[7];
        *(float4*)&g_xin[m * HID + n0 + tx * 8 + 0] = o0;
        *(float4*)&g_xin[m * HID + n0 + tx * 8 + 4] = o1;
    }
}

// ---------------------------------------------------------------------------
// Kernel 2: persistent scan — 512 threads, 16 warps (4 per SMSP).
// Warp w owns j in [16w, 16w+16). Lane = (g = lane>>3 in 0..3, ji = lane&7).
// Thread computes 2 outputs j = 16w + 8m + ji (m = 0..1) over its 64-k subset
// {32L + 8g + e : L = 0..7, e = 0..7}. Each h-load instruction covers ONE
// 128B line (4 g-chunks x 16B, 8-way ji broadcast) -> 1 wavefront.
// W: k-lines 0..1 in smem (64 KB, thread-private 128B chunks, = R4 traffic),
//    k-lines 2..7 in registers (48 u64 = 96 regs; RF-exact at 512 threads).
// Reduce over 4 k-groups = 2 butterfly shuffles (all-reduce).
// ---------------------------------------------------------------------------
#define SCAN_THREADS 512
#define WSM_LINES 2           // k-lines 0..1 from smem
#define WREG_LINES 6          // k-lines 2..7 from registers

__global__ __launch_bounds__(SCAN_THREADS, 1) void ctrnn_scan_kernel(
    const float* __restrict__ h0,
    const float* __restrict__ Wh,
    const float* __restrict__ bh,
    float* __restrict__ out,
    long long out_size)
{
    extern __shared__ float4 Wsm4[];                 // 8 * 512 float4 = 64 KB
    __shared__ __align__(128) float hbuf[2][HID];    // double-buffered h
    __shared__ float xring[2][HID];                  // xin prefetch ring

    const int tid  = threadIdx.x;
    const int b    = blockIdx.x;
    const int w    = tid >> 5;        // 0..15
    const int lane = tid & 31;
    const int g    = lane >> 3;       // 0..3  (k-group)
    const int ji   = lane & 7;        // 0..7

    // ---- stage W: smem part (k-lines 0..1), thread-private 128B chunks ----
    // chunk c = ((L*2 + m)*2 + q), q = float4 half; Wsm4[c*512 + tid]
#pragma unroll
    for (int m = 0; m < 2; m++) {
        const int j = 16 * w + 8 * m + ji;
        const float* wr = Wh + (size_t)j * HID;
#pragma unroll
        for (int L = 0; L < WSM_LINES; L++)
#pragma unroll
            for (int q = 0; q < 2; q++)
                Wsm4[(((L * 2 + m) * 2) + q) * SCAN_THREADS + tid] =
                    *(const float4*)&wr[32 * L + 8 * g + 4 * q];
    }

    // ---- stage W: register part (k-lines 2..7): 2m x 6L x 4 u64 = 48 u64 ----
    unsigned long long wreg[2][WREG_LINES][4];
#pragma unroll
    for (int m = 0; m < 2; m++) {
        const int j = 16 * w + 8 * m + ji;
        const float* wr = Wh + (size_t)j * HID;
#pragma unroll
        for (int L = 0; L < WREG_LINES; L++) {
            const ulonglong2 va =
                *(const ulonglong2*)&wr[32 * (L + WSM_LINES) + 8 * g];
            const ulonglong2 vb =
                *(const ulonglong2*)&wr[32 * (L + WSM_LINES) + 8 * g + 4];
            wreg[m][L][0] = va.x; wreg[m][L][1] = va.y;
            wreg[m][L][2] = vb.x; wreg[m][L][3] = vb.y;
        }
    }

    float bhm[2], hprev[2];
#pragma unroll
    for (int m = 0; m < 2; m++) {
        const int j = 16 * w + 8 * m + ji;
        bhm[m]   = bh[j];
        hprev[m] = h0[(size_t)b * HID + j];
    }

    const float* __restrict__ xin_b = g_xin + (size_t)b * HID;
    float* __restrict__ out_b = out + (size_t)b * HID;
    const size_t ss = (size_t)BATCH * HID;

    if (tid < HID) {
        hbuf[0][tid]  = h0[(size_t)b * HID + tid];
        xring[0][tid] = __ldg(&xin_b[tid]);           // xin for t = 0
    }
    __syncthreads();

    int p = 0;
    for (int t = 0; t < SEQ; t++) {
        const ulonglong2* __restrict__ C2 = (const ulonglong2*)hbuf[p];
        float* __restrict__ nxt = hbuf[p ^ 1];

        // prefetch next step's xin into a register (threads 0..255)
        float xnext = 0.0f;
        if (tid < HID) {
            const int tn = (t + 1 < SEQ) ? (t + 1) : t;
            xnext = __ldg(&xin_b[(size_t)tn * ss + tid]);
        }

        // 4 rotating accumulators: [m][L-parity]
        unsigned long long acc[2][2] = {{0ull, 0ull}, {0ull, 0ull}};

#pragma unroll
        for (int L = 0; L < 8; L++) {
            // thread's 8 h values on line L: 2 x LDS.128, 1 wavefront each
            const ulonglong2 ha = C2[8 * L + 2 * g + 0];
            const ulonglong2 hb = C2[8 * L + 2 * g + 1];
            const int par = L & 1;

            if (L < WSM_LINES) {
#pragma unroll
                for (int m = 0; m < 2; m++) {
                    const ulonglong2 wa = *(const ulonglong2*)
                        &Wsm4[(((L * 2 + m) * 2) + 0) * SCAN_THREADS + tid];
                    const ulonglong2 wb = *(const ulonglong2*)
                        &Wsm4[(((L * 2 + m) * 2) + 1) * SCAN_THREADS + tid];
                    ffma2(acc[m][par], wa.x, ha.x);
                    ffma2(acc[m][par], wa.y, ha.y);
                    ffma2(acc[m][par], wb.x, hb.x);
                    ffma2(acc[m][par], wb.y, hb.y);
                }
            } else {
#pragma unroll
                for (int m = 0; m < 2; m++) {
                    ffma2(acc[m][par], wreg[m][L - WSM_LINES][0], ha.x);
                    ffma2(acc[m][par], wreg[m][L - WSM_LINES][1], ha.y);
                    ffma2(acc[m][par], wreg[m][L - WSM_LINES][2], hb.x);
                    ffma2(acc[m][par], wreg[m][L - WSM_LINES][3], hb.y);
                }
            }
        }

        // all-reduce across the 4 k-groups (lane bits 3,4)
        float s[2];
#pragma unroll
        for (int m = 0; m < 2; m++) {
            float v = sum2(acc[m][0]) + sum2(acc[m][1]);
            v += __shfl_xor_sync(0xffffffffu, v, 8, 32);
            v += __shfl_xor_sync(0xffffffffu, v, 16, 32);
            s[m] = v;
        }

        // epilogue: every lane has the sums; stores predicated to g==0
#pragma unroll
        for (int m = 0; m < 2; m++) {
            const int j = 16 * w + 8 * m + ji;
            const float y  = s[m] + xring[t & 1][j] + bhm[m];
            const float hn = fmaf(fmaxf(y, 0.0f), 0.1f, 0.9f * hprev[m]);
            hprev[m] = hn;
            if (g == 0) {
                nxt[j] = hn;
                out_b[(size_t)t * ss + j] = hn;
            }
        }
        if (tid < HID) xring[(t + 1) & 1][tid] = xnext;
        p ^= 1;
        __syncthreads();
    }

    // h_final appended after outputs
    const long long main_elems = (long long)SEQ * BATCH * HID;
    if (g == 0 && out_size >= main_elems + (long long)BATCH * HID) {
#pragma unroll
        for (int m = 0; m < 2; m++)
            out[main_elems + (size_t)b * HID + 16 * w + 8 * m + ji] = hprev[m];
    }
}

// ---------------------------------------------------------------------------
// Launcher.  Inputs (metadata order): x, h0, W_in, b_in, W_h, b_h
// ---------------------------------------------------------------------------
extern "C" void kernel_launch(void* const* d_in, const int* in_sizes, int n_in,
                              void* d_out, int out_size)
{
    const float* x    = (const float*)d_in[0];
    const float* h0   = (const float*)d_in[1];
    const float* Win  = (const float*)d_in[2];
    const float* bin  = (const float*)d_in[3];
    const float* Wh   = (const float*)d_in[4];
    const float* bhp  = (const float*)d_in[5];
    float* out = (float*)d_out;

    const int scan_smem = 8 * SCAN_THREADS * (int)sizeof(float4);   // 64 KB
    cudaFuncSetAttribute(ctrnn_scan_kernel,
                         cudaFuncAttributeMaxDynamicSharedMemorySize,
                         scan_smem);

    dim3 g1((SEQ * BATCH) / GM_BM, HID / GM_BN);
    xin_gemm_kernel<<<g1, 256>>>(x, Win, bin);

    ctrnn_scan_kernel<<<BATCH, SCAN_THREADS, scan_smem>>>(
        h0, Wh, bhp, out, (long long)out_size);
}